// round 1
// baseline (speedup 1.0000x reference)
#include <cuda_runtime.h>
#include <math_constants.h>

// Shapes (fixed for this problem)
#define B_SZ   8
#define S_LEN  2048
#define E_SZ   128
#define NH     8
#define HS     16
#define ROWS_TOTAL (B_SZ * S_LEN)          // 16384
#define QT     128                          // queries per attention block
#define KT     128                          // key tile

// scale = sqrt(hs) folded with log2(e) so softmax uses ex2
#define QSCALE 5.7707801635558535f          // 4.0 * log2(e)

// -------- scratch (device globals; no allocation allowed) --------
__device__ float g_q[B_SZ * NH * S_LEN * HS];     // [b,h,s,d]
__device__ float g_k[B_SZ * NH * S_LEN * HS];
__device__ float g_v[B_SZ * NH * S_LEN * HS];
__device__ float g_ocat[ROWS_TOTAL * E_SZ];       // [b*s, h*hs]

__device__ __forceinline__ float ex2f(float x) {
    float y;
    asm("ex2.approx.ftz.f32 %0, %1;" : "=f"(y) : "f"(x));
    return y;
}

// ============================================================
// Kernel 1: fused QKV projection.
// Each block: 64 rows of x, all 128 output cols, for Wq, Wk, Wv.
// Micro-tile: 256 threads, each computes 8 rows x 4 cols.
// ============================================================
__global__ __launch_bounds__(256) void qkv_kernel(
    const float* __restrict__ x,
    const float* __restrict__ Wq,
    const float* __restrict__ Wk,
    const float* __restrict__ Wv)
{
    __shared__ float As[64 * 128];      // 32 KB   x tile
    __shared__ float Ws[16 * 132];      // 8.25 KB W chunk (transposed, padded)

    const int tid = threadIdx.x;
    const int row0 = blockIdx.x * 64;

    // load x tile (row-major contiguous)
    {
        const float4* xg = (const float4*)(x + row0 * E_SZ);
        float4* As4 = (float4*)As;
        #pragma unroll
        for (int i = 0; i < 8; i++) As4[tid + i * 256] = xg[tid + i * 256];
    }

    const int c0 = (tid & 31) * 4;       // output col base (0..124)
    const int r0 = (tid >> 5) * 8;       // local row base (0..56)

    const float* Wmats[3] = {Wq, Wk, Wv};
    float*       Omats[3] = {g_q, g_k, g_v};

    for (int mtx = 0; mtx < 3; mtx++) {
        const float* W = Wmats[mtx];
        float acc[8][4];
        #pragma unroll
        for (int rr = 0; rr < 8; rr++)
            #pragma unroll
            for (int cc = 0; cc < 4; cc++) acc[rr][cc] = 0.f;

        for (int kc = 0; kc < 8; kc++) {          // 8 chunks of 16 e's
            __syncthreads();
            // load W chunk transposed: Ws[e_local][c]
            {
                int el = tid & 15;
                int cb = tid >> 4;
                #pragma unroll
                for (int p = 0; p < 8; p++) {
                    int c = cb + p * 16;
                    Ws[el * 132 + c] = W[c * E_SZ + kc * 16 + el];
                }
            }
            __syncthreads();
            #pragma unroll
            for (int e = 0; e < 16; e++) {
                float4 wv = *(const float4*)&Ws[e * 132 + c0];
                float a[8];
                #pragma unroll
                for (int rr = 0; rr < 8; rr++)
                    a[rr] = As[(r0 + rr) * 128 + kc * 16 + e];
                #pragma unroll
                for (int rr = 0; rr < 8; rr++) {
                    acc[rr][0] = fmaf(a[rr], wv.x, acc[rr][0]);
                    acc[rr][1] = fmaf(a[rr], wv.y, acc[rr][1]);
                    acc[rr][2] = fmaf(a[rr], wv.z, acc[rr][2]);
                    acc[rr][3] = fmaf(a[rr], wv.w, acc[rr][3]);
                }
            }
        }

        // write out in [b,h,s,d] layout; q gets the folded softmax scale
        const float scl = (mtx == 0) ? QSCALE : 1.0f;
        float* OP = Omats[mtx];
        const int h = c0 >> 4;
        const int d = c0 & 15;
        #pragma unroll
        for (int rr = 0; rr < 8; rr++) {
            int row = row0 + r0 + rr;
            int b = row >> 11;           // /2048
            int s = row & 2047;
            float4 v = make_float4(acc[rr][0] * scl, acc[rr][1] * scl,
                                   acc[rr][2] * scl, acc[rr][3] * scl);
            *(float4*)&OP[(((b * NH + h) * S_LEN + s) * HS) + d] = v;
        }
    }
}

// ============================================================
// Kernel 2: flash-style attention. One block = (b, h, 128 queries),
// one thread = one query. Online softmax with 16-key register sub-tiles.
// ============================================================
__global__ __launch_bounds__(128) void att_kernel()
{
    __shared__ float Ks[KT * HS];   // 8 KB
    __shared__ float Vs[KT * HS];   // 8 KB

    const int tid = threadIdx.x;
    const int bid = blockIdx.x;
    const int qt = bid & 15;            // S/QT = 16
    const int h  = (bid >> 4) & 7;
    const int b  = bid >> 7;
    const int bh = b * NH + h;
    const int s  = qt * QT + tid;

    float4 qr[4];
    {
        const float4* qg = (const float4*)(g_q + (bh * S_LEN + s) * HS);
        #pragma unroll
        for (int t = 0; t < 4; t++) qr[t] = qg[t];
    }
    float4 orr[4];
    #pragma unroll
    for (int t = 0; t < 4; t++) orr[t] = make_float4(0.f, 0.f, 0.f, 0.f);
    float m = -CUDART_INF_F;
    float l = 0.f;

    const float4* Kg = (const float4*)(g_k + bh * S_LEN * HS);
    const float4* Vg = (const float4*)(g_v + bh * S_LEN * HS);
    float4* Ks4 = (float4*)Ks;
    float4* Vs4 = (float4*)Vs;

    for (int kt0 = 0; kt0 < S_LEN / KT; kt0++) {
        __syncthreads();
        #pragma unroll
        for (int i = 0; i < 4; i++) {
            int idx = tid + i * 128;
            Ks4[idx] = Kg[kt0 * 512 + idx];
            Vs4[idx] = Vg[kt0 * 512 + idx];
        }
        __syncthreads();

        #pragma unroll
        for (int sub = 0; sub < KT / 16; sub++) {
            float sc[16];
            float tmax = -CUDART_INF_F;
            #pragma unroll
            for (int jj = 0; jj < 16; jj++) {
                int j = sub * 16 + jj;
                float sv = 0.f;
                #pragma unroll
                for (int t = 0; t < 4; t++) {
                    float4 kv = Ks4[j * 4 + t];
                    sv = fmaf(qr[t].x, kv.x, sv);
                    sv = fmaf(qr[t].y, kv.y, sv);
                    sv = fmaf(qr[t].z, kv.z, sv);
                    sv = fmaf(qr[t].w, kv.w, sv);
                }
                sc[jj] = sv;
                tmax = fmaxf(tmax, sv);
            }
            // rescale (warp-mostly-uniform, rarely taken after warm-up)
            if (tmax > m) {
                float c = ex2f(m - tmax);   // 0 on first hit (m = -inf)
                l *= c;
                #pragma unroll
                for (int t = 0; t < 4; t++) {
                    orr[t].x *= c; orr[t].y *= c; orr[t].z *= c; orr[t].w *= c;
                }
                m = tmax;
            }
            #pragma unroll
            for (int jj = 0; jj < 16; jj++) {
                int j = sub * 16 + jj;
                float p = ex2f(sc[jj] - m);
                l += p;
                #pragma unroll
                for (int t = 0; t < 4; t++) {
                    float4 vv = Vs4[j * 4 + t];
                    orr[t].x = fmaf(p, vv.x, orr[t].x);
                    orr[t].y = fmaf(p, vv.y, orr[t].y);
                    orr[t].z = fmaf(p, vv.z, orr[t].z);
                    orr[t].w = fmaf(p, vv.w, orr[t].w);
                }
            }
        }
    }

    const float inv = 1.0f / l;
    float4* og = (float4*)(g_ocat + (b * S_LEN + s) * E_SZ + h * HS);
    #pragma unroll
    for (int t = 0; t < 4; t++) {
        og[t] = make_float4(orr[t].x * inv, orr[t].y * inv,
                            orr[t].z * inv, orr[t].w * inv);
    }
}

// ============================================================
// Kernel 3: output projection  out = o_cat @ Wp^T + bp
// Same micro-tile structure as qkv_kernel, single matrix + bias.
// ============================================================
__global__ __launch_bounds__(256) void proj_kernel(
    const float* __restrict__ Wp,
    const float* __restrict__ bp,
    float* __restrict__ out)
{
    __shared__ float As[64 * 128];
    __shared__ float Ws[16 * 132];

    const int tid = threadIdx.x;
    const int row0 = blockIdx.x * 64;

    {
        const float4* xg = (const float4*)(g_ocat + row0 * E_SZ);
        float4* As4 = (float4*)As;
        #pragma unroll
        for (int i = 0; i < 8; i++) As4[tid + i * 256] = xg[tid + i * 256];
    }

    const int c0 = (tid & 31) * 4;
    const int r0 = (tid >> 5) * 8;

    float acc[8][4];
    #pragma unroll
    for (int rr = 0; rr < 8; rr++)
        #pragma unroll
        for (int cc = 0; cc < 4; cc++) acc[rr][cc] = 0.f;

    for (int kc = 0; kc < 8; kc++) {
        __syncthreads();
        {
            int el = tid & 15;
            int cb = tid >> 4;
            #pragma unroll
            for (int p = 0; p < 8; p++) {
                int c = cb + p * 16;
                Ws[el * 132 + c] = Wp[c * E_SZ + kc * 16 + el];
            }
        }
        __syncthreads();
        #pragma unroll
        for (int e = 0; e < 16; e++) {
            float4 wv = *(const float4*)&Ws[e * 132 + c0];
            float a[8];
            #pragma unroll
            for (int rr = 0; rr < 8; rr++)
                a[rr] = As[(r0 + rr) * 128 + kc * 16 + e];
            #pragma unroll
            for (int rr = 0; rr < 8; rr++) {
                acc[rr][0] = fmaf(a[rr], wv.x, acc[rr][0]);
                acc[rr][1] = fmaf(a[rr], wv.y, acc[rr][1]);
                acc[rr][2] = fmaf(a[rr], wv.z, acc[rr][2]);
                acc[rr][3] = fmaf(a[rr], wv.w, acc[rr][3]);
            }
        }
    }

    const float4 bias = *(const float4*)&bp[c0];
    #pragma unroll
    for (int rr = 0; rr < 8; rr++) {
        int row = row0 + r0 + rr;
        float4 v = make_float4(acc[rr][0] + bias.x, acc[rr][1] + bias.y,
                               acc[rr][2] + bias.z, acc[rr][3] + bias.w);
        *(float4*)&out[row * E_SZ + c0] = v;
    }
}

// ============================================================
// launch: inputs are (x, Wk, Wq, Wv, Wp, bp) per metadata order
// ============================================================
extern "C" void kernel_launch(void* const* d_in, const int* in_sizes, int n_in,
                              void* d_out, int out_size)
{
    const float* x  = (const float*)d_in[0];
    const float* Wk = (const float*)d_in[1];
    const float* Wq = (const float*)d_in[2];
    const float* Wv = (const float*)d_in[3];
    const float* Wp = (const float*)d_in[4];
    const float* bp = (const float*)d_in[5];
    float* out = (float*)d_out;

    qkv_kernel<<<ROWS_TOTAL / 64, 256>>>(x, Wq, Wk, Wv);
    att_kernel<<<B_SZ * NH * (S_LEN / QT), 128>>>();
    proj_kernel<<<ROWS_TOTAL / 64, 256>>>(Wp, bp, out);
}

// round 3
// speedup vs baseline: 3.4057x; 3.4057x over previous
#include <cuda_runtime.h>
#include <cstdint>

// Shapes (fixed for this problem)
#define B_SZ   8
#define S_LEN  2048
#define E_SZ   128
#define NH     8
#define HS     16
#define ROWS_TOTAL (B_SZ * S_LEN)          // 16384

// softmax in base-2: fold scale = sqrt(hs)*log2(e) into Q
#define QSCALE 5.7707801635558535f          // 4 * log2(e)

// -------- scratch (device globals; no allocation allowed) --------
__device__ float g_q[B_SZ * NH * S_LEN * HS];     // [b,h,s,d]  (pre-scaled by QSCALE)
__device__ float g_k[B_SZ * NH * S_LEN * HS];
__device__ float g_v[B_SZ * NH * S_LEN * HS];
__device__ float g_ocat[ROWS_TOTAL * E_SZ];       // [b*s, h*hs]

// ================= helpers =================
__device__ __forceinline__ float ex2f(float x) {
    float y; asm("ex2.approx.ftz.f32 %0, %1;" : "=f"(y) : "f"(x)); return y;
}
__device__ __forceinline__ uint32_t smem_to_u32(const void* p) {
    uint32_t a;
    asm("{ .reg .u64 t; cvta.to.shared.u64 t, %1; cvt.u32.u64 %0, t; }" : "=r"(a) : "l"(p));
    return a;
}
// pack: lower 16 bits = bf16(a), upper = bf16(b)
#define CVT_BF16X2_F32(result, a, b) \
    asm("cvt.rn.satfinite.bf16x2.f32 %0, %1, %2;" : "=r"(result) : "f"(b), "f"(a))

// split fp32 pair -> (bf16x2 hi, bf16x2 lo)
__device__ __forceinline__ void split_pair(float a, float c, uint32_t& hi, uint32_t& lo) {
    CVT_BF16X2_F32(hi, a, c);
    float ar = a - __uint_as_float(hi << 16);
    float cr = c - __uint_as_float(hi & 0xffff0000u);
    CVT_BF16X2_F32(lo, ar, cr);
}

__device__ __forceinline__ void mma16816(float* c, const uint32_t* a, uint32_t b0, uint32_t b1) {
    asm volatile("mma.sync.aligned.m16n8k16.row.col.f32.bf16.bf16.f32 "
        "{%0,%1,%2,%3}, {%4,%5,%6,%7}, {%8,%9}, {%0,%1,%2,%3};"
        : "+f"(c[0]), "+f"(c[1]), "+f"(c[2]), "+f"(c[3])
        : "r"(a[0]), "r"(a[1]), "r"(a[2]), "r"(a[3]), "r"(b0), "r"(b1));
}
__device__ __forceinline__ void ldsm_x2(uint32_t& r0, uint32_t& r1, uint32_t addr) {
    asm volatile("ldmatrix.sync.aligned.m8n8.x2.shared.b16 {%0,%1}, [%2];"
        : "=r"(r0), "=r"(r1) : "r"(addr));
}
__device__ __forceinline__ void ldsm_x2_t(uint32_t& r0, uint32_t& r1, uint32_t addr) {
    asm volatile("ldmatrix.sync.aligned.m8n8.x2.trans.shared.b16 {%0,%1}, [%2];"
        : "=r"(r0), "=r"(r1) : "r"(addr));
}

// ============================================================
// Kernel 1: fused QKV projection (Q pre-scaled by QSCALE)
// ============================================================
__global__ __launch_bounds__(256) void qkv_kernel(
    const float* __restrict__ x,
    const float* __restrict__ Wq,
    const float* __restrict__ Wk,
    const float* __restrict__ Wv)
{
    __shared__ float As[64 * 128];
    __shared__ float Ws[16 * 132];

    const int tid = threadIdx.x;
    const int row0 = blockIdx.x * 64;

    {
        const float4* xg = (const float4*)(x + row0 * E_SZ);
        float4* As4 = (float4*)As;
        #pragma unroll
        for (int i = 0; i < 8; i++) As4[tid + i * 256] = xg[tid + i * 256];
    }

    const int c0 = (tid & 31) * 4;
    const int r0 = (tid >> 5) * 8;

    const float* Wmats[3] = {Wq, Wk, Wv};
    float*       Omats[3] = {g_q, g_k, g_v};

    for (int mtx = 0; mtx < 3; mtx++) {
        const float* W = Wmats[mtx];
        float acc[8][4];
        #pragma unroll
        for (int rr = 0; rr < 8; rr++)
            #pragma unroll
            for (int cc = 0; cc < 4; cc++) acc[rr][cc] = 0.f;

        for (int kc = 0; kc < 8; kc++) {
            __syncthreads();
            {
                int el = tid & 15;
                int cb = tid >> 4;
                #pragma unroll
                for (int p = 0; p < 8; p++) {
                    int c = cb + p * 16;
                    Ws[el * 132 + c] = W[c * E_SZ + kc * 16 + el];
                }
            }
            __syncthreads();
            #pragma unroll
            for (int e = 0; e < 16; e++) {
                float4 wv = *(const float4*)&Ws[e * 132 + c0];
                float a[8];
                #pragma unroll
                for (int rr = 0; rr < 8; rr++)
                    a[rr] = As[(r0 + rr) * 128 + kc * 16 + e];
                #pragma unroll
                for (int rr = 0; rr < 8; rr++) {
                    acc[rr][0] = fmaf(a[rr], wv.x, acc[rr][0]);
                    acc[rr][1] = fmaf(a[rr], wv.y, acc[rr][1]);
                    acc[rr][2] = fmaf(a[rr], wv.z, acc[rr][2]);
                    acc[rr][3] = fmaf(a[rr], wv.w, acc[rr][3]);
                }
            }
        }

        const float scl = (mtx == 0) ? QSCALE : 1.0f;
        float* OP = Omats[mtx];
        const int h = c0 >> 4;
        const int d = c0 & 15;
        #pragma unroll
        for (int rr = 0; rr < 8; rr++) {
            int row = row0 + r0 + rr;
            int b = row >> 11;
            int s = row & 2047;
            float4 v = make_float4(acc[rr][0] * scl, acc[rr][1] * scl,
                                   acc[rr][2] * scl, acc[rr][3] * scl);
            *(float4*)&OP[(((b * NH + h) * S_LEN + s) * HS) + d] = v;
        }
    }
}

// ============================================================
// Kernel 2: FA2-style HMMA flash attention.
// CTA = (b, h, 128 queries); 4 warps x 32 queries; key tile 64.
// Split bf16: QK^T = QhKh + QlKh + QhKl; PV = P(Vh + Vl).
// ============================================================
__global__ __launch_bounds__(128) void att_mma_kernel()
{
    // rows padded to 24 halves (48B) -> conflict-free ldmatrix
    __shared__ __align__(16) uint16_t sKh[64 * 24];
    __shared__ __align__(16) uint16_t sKl[64 * 24];
    __shared__ __align__(16) uint16_t sVh[64 * 24];
    __shared__ __align__(16) uint16_t sVl[64 * 24];

    const int tid  = threadIdx.x;
    const int warp = tid >> 5;
    const int lane = tid & 31;
    const int g = lane >> 2;         // groupID (row within 8)
    const int t = lane & 3;          // thread in group (col pair)
    const int bid = blockIdx.x;
    const int qt = bid & 15;
    const int h  = (bid >> 4) & 7;
    const int b  = bid >> 7;
    const int bh = b * NH + h;
    const int qbase = qt * 128 + warp * 32;

    // ---- Q fragments (resident; 2 m-tiles, hi+lo split) ----
    uint32_t qh[2][4], ql[2][4];
    {
        const float* Qg = g_q + (size_t)bh * S_LEN * HS;
        #pragma unroll
        for (int mt = 0; mt < 2; mt++) {
            int rA = qbase + mt * 16 + g;
            int rB = rA + 8;
            float2 a0 = *(const float2*)(Qg + rA * HS + 2 * t);
            float2 a1 = *(const float2*)(Qg + rB * HS + 2 * t);
            float2 a2 = *(const float2*)(Qg + rA * HS + 2 * t + 8);
            float2 a3 = *(const float2*)(Qg + rB * HS + 2 * t + 8);
            split_pair(a0.x, a0.y, qh[mt][0], ql[mt][0]);
            split_pair(a1.x, a1.y, qh[mt][1], ql[mt][1]);
            split_pair(a2.x, a2.y, qh[mt][2], ql[mt][2]);
            split_pair(a3.x, a3.y, qh[mt][3], ql[mt][3]);
        }
    }

    float o[2][2][4];
    #pragma unroll
    for (int mt = 0; mt < 2; mt++)
        #pragma unroll
        for (int nO = 0; nO < 2; nO++)
            #pragma unroll
            for (int j = 0; j < 4; j++) o[mt][nO][j] = 0.f;
    float m[4] = {-1e30f, -1e30f, -1e30f, -1e30f};
    float l[4] = {0.f, 0.f, 0.f, 0.f};

    const uint32_t kh_b = smem_to_u32(sKh), kl_b = smem_to_u32(sKl);
    const uint32_t vh_b = smem_to_u32(sVh), vl_b = smem_to_u32(sVl);
    const int l15 = lane & 15;
    // K (non-trans) per-lane offset: row = n*8 + (lane&7), 16B col-half by bit3
    const uint32_t k_off = (uint32_t)((lane & 7) * 48 + ((l15 >> 3) << 4));
    // V (trans) per-lane offset: row = ks*16 + (lane&15)
    const uint32_t v_off = (uint32_t)(l15 * 48);

    const int r  = tid >> 1;        // key row this thread loads
    const int hf = tid & 1;         // which 8-wide half of hs
    const float* Ksrc0 = g_k + ((size_t)bh * S_LEN + r) * HS + hf * 8;
    const float* Vsrc0 = g_v + ((size_t)bh * S_LEN + r) * HS + hf * 8;
    char* kh_st = (char*)sKh + r * 48 + hf * 16;
    char* kl_st = (char*)sKl + r * 48 + hf * 16;
    char* vh_st = (char*)sVh + r * 48 + hf * 16;
    char* vl_st = (char*)sVl + r * 48 + hf * 16;

    for (int kt = 0; kt < S_LEN / 64; kt++) {
        __syncthreads();   // previous tile fully consumed
        // ---- load K,V tile -> split bf16 -> smem ----
        {
            const float* Ks = Ksrc0 + (size_t)kt * 64 * HS;
            float4 f0 = *(const float4*)Ks;
            float4 f1 = *(const float4*)(Ks + 4);
            uint32_t h0,h1,h2,h3, L0,L1,L2,L3;
            split_pair(f0.x, f0.y, h0, L0); split_pair(f0.z, f0.w, h1, L1);
            split_pair(f1.x, f1.y, h2, L2); split_pair(f1.z, f1.w, h3, L3);
            *(uint4*)kh_st = make_uint4(h0, h1, h2, h3);
            *(uint4*)kl_st = make_uint4(L0, L1, L2, L3);

            const float* Vs = Vsrc0 + (size_t)kt * 64 * HS;
            float4 g0 = *(const float4*)Vs;
            float4 g1 = *(const float4*)(Vs + 4);
            split_pair(g0.x, g0.y, h0, L0); split_pair(g0.z, g0.w, h1, L1);
            split_pair(g1.x, g1.y, h2, L2); split_pair(g1.z, g1.w, h3, L3);
            *(uint4*)vh_st = make_uint4(h0, h1, h2, h3);
            *(uint4*)vl_st = make_uint4(L0, L1, L2, L3);
        }
        __syncthreads();   // tile ready

        // ---- S = Q K^T over 8 n-tiles of 8 keys ----
        float sc[2][8][4];
        #pragma unroll
        for (int mt = 0; mt < 2; mt++)
            #pragma unroll
            for (int n = 0; n < 8; n++)
                #pragma unroll
                for (int j = 0; j < 4; j++) sc[mt][n][j] = 0.f;

        #pragma unroll
        for (int n = 0; n < 8; n++) {
            uint32_t kh0, kh1, kl0, kl1;
            ldsm_x2(kh0, kh1, kh_b + n * (8 * 48) + k_off);
            ldsm_x2(kl0, kl1, kl_b + n * (8 * 48) + k_off);
            #pragma unroll
            for (int mt = 0; mt < 2; mt++) {
                mma16816(sc[mt][n], qh[mt], kh0, kh1);
                mma16816(sc[mt][n], ql[mt], kh0, kh1);
                mma16816(sc[mt][n], qh[mt], kl0, kl1);
            }
        }

        // ---- online softmax (rows g / g+8 per m-tile; reduce over quad) ----
        #pragma unroll
        for (int mt = 0; mt < 2; mt++) {
            float mxt = -1e30f, mxb = -1e30f;
            #pragma unroll
            for (int n = 0; n < 8; n++) {
                mxt = fmaxf(mxt, fmaxf(sc[mt][n][0], sc[mt][n][1]));
                mxb = fmaxf(mxb, fmaxf(sc[mt][n][2], sc[mt][n][3]));
            }
            mxt = fmaxf(mxt, __shfl_xor_sync(0xffffffffu, mxt, 1));
            mxt = fmaxf(mxt, __shfl_xor_sync(0xffffffffu, mxt, 2));
            mxb = fmaxf(mxb, __shfl_xor_sync(0xffffffffu, mxb, 1));
            mxb = fmaxf(mxb, __shfl_xor_sync(0xffffffffu, mxb, 2));

            const int st = mt * 2, sbo = mt * 2 + 1;
            float mnt = fmaxf(m[st],  mxt);
            float mnb = fmaxf(m[sbo], mxb);
            float ct = ex2f(m[st]  - mnt);
            float cb = ex2f(m[sbo] - mnb);
            m[st] = mnt; m[sbo] = mnb;
            l[st] *= ct; l[sbo] *= cb;
            #pragma unroll
            for (int nO = 0; nO < 2; nO++) {
                o[mt][nO][0] *= ct; o[mt][nO][1] *= ct;
                o[mt][nO][2] *= cb; o[mt][nO][3] *= cb;
            }
            float lt = 0.f, lb = 0.f;
            #pragma unroll
            for (int n = 0; n < 8; n++) {
                sc[mt][n][0] = ex2f(sc[mt][n][0] - mnt);
                sc[mt][n][1] = ex2f(sc[mt][n][1] - mnt);
                sc[mt][n][2] = ex2f(sc[mt][n][2] - mnb);
                sc[mt][n][3] = ex2f(sc[mt][n][3] - mnb);
                lt += sc[mt][n][0] + sc[mt][n][1];
                lb += sc[mt][n][2] + sc[mt][n][3];
            }
            l[st] += lt; l[sbo] += lb;
        }

        // ---- O += P V  (P from score regs, V via trans ldmatrix) ----
        #pragma unroll
        for (int ks = 0; ks < 4; ks++) {
            uint32_t pa[2][4];
            #pragma unroll
            for (int mt = 0; mt < 2; mt++) {
                CVT_BF16X2_F32(pa[mt][0], sc[mt][2*ks  ][0], sc[mt][2*ks  ][1]);
                CVT_BF16X2_F32(pa[mt][1], sc[mt][2*ks  ][2], sc[mt][2*ks  ][3]);
                CVT_BF16X2_F32(pa[mt][2], sc[mt][2*ks+1][0], sc[mt][2*ks+1][1]);
                CVT_BF16X2_F32(pa[mt][3], sc[mt][2*ks+1][2], sc[mt][2*ks+1][3]);
            }
            #pragma unroll
            for (int nO = 0; nO < 2; nO++) {
                uint32_t vh0, vh1, vl0, vl1;
                ldsm_x2_t(vh0, vh1, vh_b + ks * (16 * 48) + v_off + nO * 16);
                ldsm_x2_t(vl0, vl1, vl_b + ks * (16 * 48) + v_off + nO * 16);
                mma16816(o[0][nO], pa[0], vh0, vh1);
                mma16816(o[0][nO], pa[0], vl0, vl1);
                mma16816(o[1][nO], pa[1], vh0, vh1);
                mma16816(o[1][nO], pa[1], vl0, vl1);
            }
        }
    }

    // ---- epilogue: finish row sums, normalize, write concat layout ----
    #pragma unroll
    for (int s = 0; s < 4; s++) {
        l[s] += __shfl_xor_sync(0xffffffffu, l[s], 1);
        l[s] += __shfl_xor_sync(0xffffffffu, l[s], 2);
    }
    #pragma unroll
    for (int mt = 0; mt < 2; mt++) {
        int rT = qbase + mt * 16 + g;
        int rB = rT + 8;
        float iT = 1.0f / l[mt * 2];
        float iB = 1.0f / l[mt * 2 + 1];
        #pragma unroll
        for (int nO = 0; nO < 2; nO++) {
            float* pT = g_ocat + ((size_t)b * S_LEN + rT) * E_SZ + h * HS + nO * 8 + 2 * t;
            float* pB = g_ocat + ((size_t)b * S_LEN + rB) * E_SZ + h * HS + nO * 8 + 2 * t;
            *(float2*)pT = make_float2(o[mt][nO][0] * iT, o[mt][nO][1] * iT);
            *(float2*)pB = make_float2(o[mt][nO][2] * iB, o[mt][nO][3] * iB);
        }
    }
}

// ============================================================
// Kernel 3: output projection  out = o_cat @ Wp^T + bp
// ============================================================
__global__ __launch_bounds__(256) void proj_kernel(
    const float* __restrict__ Wp,
    const float* __restrict__ bp,
    float* __restrict__ out)
{
    __shared__ float As[64 * 128];
    __shared__ float Ws[16 * 132];

    const int tid = threadIdx.x;
    const int row0 = blockIdx.x * 64;

    {
        const float4* xg = (const float4*)(g_ocat + row0 * E_SZ);
        float4* As4 = (float4*)As;
        #pragma unroll
        for (int i = 0; i < 8; i++) As4[tid + i * 256] = xg[tid + i * 256];
    }

    const int c0 = (tid & 31) * 4;
    const int r0 = (tid >> 5) * 8;

    float acc[8][4];
    #pragma unroll
    for (int rr = 0; rr < 8; rr++)
        #pragma unroll
        for (int cc = 0; cc < 4; cc++) acc[rr][cc] = 0.f;

    for (int kc = 0; kc < 8; kc++) {
        __syncthreads();
        {
            int el = tid & 15;
            int cb = tid >> 4;
            #pragma unroll
            for (int p = 0; p < 8; p++) {
                int c = cb + p * 16;
                Ws[el * 132 + c] = Wp[c * E_SZ + kc * 16 + el];
            }
        }
        __syncthreads();
        #pragma unroll
        for (int e = 0; e < 16; e++) {
            float4 wv = *(const float4*)&Ws[e * 132 + c0];
            float a[8];
            #pragma unroll
            for (int rr = 0; rr < 8; rr++)
                a[rr] = As[(r0 + rr) * 128 + kc * 16 + e];
            #pragma unroll
            for (int rr = 0; rr < 8; rr++) {
                acc[rr][0] = fmaf(a[rr], wv.x, acc[rr][0]);
                acc[rr][1] = fmaf(a[rr], wv.y, acc[rr][1]);
                acc[rr][2] = fmaf(a[rr], wv.z, acc[rr][2]);
                acc[rr][3] = fmaf(a[rr], wv.w, acc[rr][3]);
            }
        }
    }

    const float4 bias = *(const float4*)&bp[c0];
    #pragma unroll
    for (int rr = 0; rr < 8; rr++) {
        int row = row0 + r0 + rr;
        float4 v = make_float4(acc[rr][0] + bias.x, acc[rr][1] + bias.y,
                               acc[rr][2] + bias.z, acc[rr][3] + bias.w);
        *(float4*)&out[row * E_SZ + c0] = v;
    }
}

// ============================================================
// launch: inputs are (x, Wk, Wq, Wv, Wp, bp) per metadata order
// ============================================================
extern "C" void kernel_launch(void* const* d_in, const int* in_sizes, int n_in,
                              void* d_out, int out_size)
{
    const float* x  = (const float*)d_in[0];
    const float* Wk = (const float*)d_in[1];
    const float* Wq = (const float*)d_in[2];
    const float* Wv = (const float*)d_in[3];
    const float* Wp = (const float*)d_in[4];
    const float* bp = (const float*)d_in[5];
    float* out = (float*)d_out;

    qkv_kernel<<<ROWS_TOTAL / 64, 256>>>(x, Wq, Wk, Wv);
    att_mma_kernel<<<B_SZ * NH * (S_LEN / 128), 128>>>();
    proj_kernel<<<ROWS_TOTAL / 64, 256>>>(Wp, bp, out);
}